// round 1
// baseline (speedup 1.0000x reference)
#include <cuda_runtime.h>

#define HH 256
#define WW 256
#define NBLK 63
#define CAND 81
#define KSEL 16
#define NIMG 8

// Scratch (static __device__ — no allocations)
__device__ __align__(16) float g_T[NIMG * NBLK * NBLK * 64];   // per-patch 8x8 DCT coeffs
__device__ __align__(16) float g_nc[NIMG * HH * WW * 2];       // interleaved {num, cnt}

// ---------------------------------------------------------------------------
// Kernel 0: zero the accumulator
// ---------------------------------------------------------------------------
__global__ void zero_kernel() {
    int idx = blockIdx.x * blockDim.x + threadIdx.x;  // 262144 float4s
    ((float4*)g_nc)[idx] = make_float4(0.f, 0.f, 0.f, 0.f);
}

// ---------------------------------------------------------------------------
// Kernel 1: 8x8 DCT of every patch (4 patches per 256-thread CTA)
// ---------------------------------------------------------------------------
__global__ void dct_kernel(const float* __restrict__ x) {
    __shared__ float sD[64];
    __shared__ float sp[4][64];
    __shared__ float st[4][64];
    int t = threadIdx.x;
    if (t < 64) {
        int k = t >> 3, i = t & 7;
        float v = cospif((float)((2 * i + 1) * k) / 16.0f) * 0.5f;
        if (k == 0) v = 0.35355339059327373f;
        sD[t] = v;
    }
    int grp = t >> 6;
    int lt = t & 63;
    int pid = blockIdx.x * 4 + grp;
    bool valid = pid < NIMG * NBLK * NBLK;
    int img = 0, bi = 0, bj = 0;
    if (valid) {
        img = pid / (NBLK * NBLK);
        int r = pid % (NBLK * NBLK);
        bi = r / NBLK; bj = r % NBLK;
    }
    __syncthreads();
    if (valid) {
        int b = lt >> 3, c = lt & 7;
        float v = x[img * (HH * WW) + (bi * 4 + b) * WW + (bj * 4 + c)];
        sp[grp][lt] = fminf(fmaxf(v, 0.0f), 1.0f);
    }
    __syncthreads();
    if (valid) {
        int a = lt >> 3, c = lt & 7;
        float acc = 0.f;
#pragma unroll
        for (int b = 0; b < 8; b++) acc += sD[a * 8 + b] * sp[grp][b * 8 + c];
        st[grp][lt] = acc;
    }
    __syncthreads();
    if (valid) {
        int a = lt >> 3, d = lt & 7;
        float acc = 0.f;
#pragma unroll
        for (int c = 0; c < 8; c++) acc += st[grp][a * 8 + c] * sD[d * 8 + c];
        g_T[pid * 64 + lt] = acc;
    }
}

// ---------------------------------------------------------------------------
// Kernel 2: main BM3D pipeline. One CTA handles 4 reference blocks (same i),
// with the 9x12 T-neighborhood staged in shared memory.
// ---------------------------------------------------------------------------
__global__ void __launch_bounds__(128) bm3d_kernel() {
    __shared__ float nbT[9 * 12 * 64];      // 27648 B
    __shared__ float GA[16 * 64];
    __shared__ float GB[16 * 64];
    __shared__ float sDK[256];
    __shared__ float sD[64];
    __shared__ float sdist[CAND];
    __shared__ int selOff[KSEL];
    __shared__ int selYs[KSEL];
    __shared__ int selXs[KSEL];
    __shared__ int snnz;

    int t = threadIdx.x;
    int i = blockIdx.y;
    int j0 = blockIdx.x * 4;
    int img = blockIdx.z;
    int nb = min(4, NBLK - j0);

    if (t < 64) {
        int k = t >> 3, ii = t & 7;
        float v = cospif((float)((2 * ii + 1) * k) / 16.0f) * 0.5f;
        if (k == 0) v = 0.35355339059327373f;
        sD[t] = v;
    }
    for (int u = t; u < 256; u += 128) {
        int k = u >> 4, ii = u & 15;
        float v = cospif((float)((2 * ii + 1) * k) / 32.0f) * 0.35355339059327373f;
        if (k == 0) v = 0.25f;
        sDK[u] = v;
    }
    const float* Timg = g_T + img * (NBLK * NBLK * 64);
    for (int idx = t; idx < 9 * 12 * 64; idx += 128) {
        int r = idx / (12 * 64);
        int s = (idx >> 6) % 12;
        int p = idx & 63;
        int ci = min(max(i - 4 + r, 0), NBLK - 1);
        int cj = min(max(j0 - 4 + s, 0), NBLK - 1);
        nbT[idx] = Timg[(ci * NBLK + cj) * 64 + p];
    }
    __syncthreads();

    int lane = t & 31, warp = t >> 5;
    float* ncImg = g_nc + img * (HH * WW * 2);

    for (int jb = 0; jb < nb; jb++) {
        int j = j0 + jb;
        int sref = jb + 4;
        float r0 = nbT[(4 * 12 + sref) * 64 + 2 * lane];
        float r1 = nbT[(4 * 12 + sref) * 64 + 2 * lane + 1];
        if (t == 0) snnz = 0;

        // --- candidate distances (exact duplicates stay bit-identical) ---
        for (int c = warp; c < CAND; c += 4) {
            int rr = c / 9;
            int sc = jb + (c % 9);
            const float* cp = &nbT[(rr * 12 + sc) * 64];
            float d0 = cp[2 * lane] - r0;
            float d1 = cp[2 * lane + 1] - r1;
            float dd = d0 * d0 + d1 * d1;
#pragma unroll
            for (int o = 16; o > 0; o >>= 1) dd += __shfl_xor_sync(0xffffffffu, dd, o);
            if (lane == 0) sdist[c] = dd;
        }
        __syncthreads();

        // --- rank-based top-16, ties -> lower candidate index (JAX top_k) ---
        if (t < CAND) {
            float my = sdist[t];
            int rank = 0;
            for (int c = 0; c < CAND; c++) {
                float dc = sdist[c];
                rank += (dc < my) || (dc == my && c < t);
            }
            if (rank < KSEL) {
                int rr = t / 9;
                int dx = t % 9;
                selOff[rank] = (rr * 12 + jb + dx) * 64;
                int ci = min(max(i - 4 + rr, 0), NBLK - 1);
                int cj = min(max(j - 4 + dx, 0), NBLK - 1);
                selYs[rank] = ci * 4;
                selXs[rank] = cj * 4;
            }
        }
        __syncthreads();

        // --- forward 16-pt DCT along group axis + hard threshold + nnz ---
        {
            int p = t & 63, half = t >> 6;
            float g[16];
#pragma unroll
            for (int k = 0; k < 16; k++) g[k] = nbT[selOff[k] + p];
            int cnt = 0;
#pragma unroll
            for (int q = 0; q < 8; q++) {
                int l = half * 8 + q;
                float acc = 0.f;
#pragma unroll
                for (int k = 0; k < 16; k++) acc += sDK[l * 16 + k] * g[k];
                bool m = fabsf(acc) > 0.135f;
                cnt += m ? 1 : 0;
                GA[l * 64 + p] = m ? acc : 0.0f;
            }
            atomicAdd(&snnz, cnt);
        }
        __syncthreads();
        float wgt = 400.0f / fmaxf((float)snnz, 1.0f);

        // --- "inverse" along group axis: reference applies DK AGAIN (not DK^T) ---
        {
            int p = t & 63, half = t >> 6;
            float g[16];
#pragma unroll
            for (int k = 0; k < 16; k++) g[k] = GA[k * 64 + p];
#pragma unroll
            for (int q = 0; q < 8; q++) {
                int l = half * 8 + q;
                float acc = 0.f;
#pragma unroll
                for (int k = 0; k < 16; k++) acc += sDK[l * 16 + k] * g[k];
                GB[l * 64 + p] = acc;
            }
        }
        __syncthreads();

        // --- 2D inverse stage 1: tmp[a][y] = sum_d G[a][d] * D[d][y] ---
        {
            int p = t & 63, half = t >> 6;
            int a = p >> 3, y = p & 7;
#pragma unroll
            for (int q = 0; q < 8; q++) {
                int k = half * 8 + q;
                float acc = 0.f;
#pragma unroll
                for (int d = 0; d < 8; d++) acc += GB[k * 64 + a * 8 + d] * sD[d * 8 + y];
                GA[k * 64 + p] = acc;
            }
        }
        __syncthreads();

        // --- 2D inverse stage 2 fused with weighted scatter (float4 atomics) ---
        {
            for (int item = t; item < 512; item += 128) {
                int k = item >> 5;
                int rem = item & 31;
                int b = rem >> 2;           // output patch row
                int cp2 = (rem & 3) * 2;    // even output column within patch
                float a0 = 0.f, a1 = 0.f;
#pragma unroll
                for (int a = 0; a < 8; a++) {
                    float dv = sD[a * 8 + b];
                    a0 += dv * GA[k * 64 + a * 8 + cp2];
                    a1 += dv * GA[k * 64 + a * 8 + cp2 + 1];
                }
                int row = selYs[k] + b;
                int col = selXs[k] + cp2;
                float4 v = make_float4(wgt * a0, wgt, wgt * a1, wgt);
                atomicAdd((float4*)(ncImg + (row * WW + col) * 2), v);
            }
        }
        __syncthreads();
    }
}

// ---------------------------------------------------------------------------
// Kernel 3: final divide
// ---------------------------------------------------------------------------
__global__ void div_kernel(float* __restrict__ out) {
    int idx = blockIdx.x * blockDim.x + threadIdx.x;  // 524288 pixels
    float2 v = ((float2*)g_nc)[idx];
    out[idx] = v.x / fmaxf(v.y, 1e-8f);
}

// ---------------------------------------------------------------------------
extern "C" void kernel_launch(void* const* d_in, const int* in_sizes, int n_in,
                              void* d_out, int out_size) {
    const float* x = (const float*)d_in[0];
    (void)in_sizes; (void)n_in; (void)out_size;

    zero_kernel<<<1024, 256>>>();
    dct_kernel<<<(NIMG * NBLK * NBLK + 3) / 4, 256>>>(x);
    bm3d_kernel<<<dim3(16, NBLK, NIMG), 128>>>();
    div_kernel<<<2048, 256>>>((float*)d_out);
}